// round 16
// baseline (speedup 1.0000x reference)
#include <cuda_runtime.h>
#include <cuda_bf16.h>

#define NT   256
#define SEQ  1024
#define NB   64

// Precomputed exp(transitions) packed by row-pairs (bf16):
// g_Epack[k*NT + j] = bf162( exp(T[2k][j]), exp(T[2k+1][j]) )
__device__ __nv_bfloat162 g_Epack[128 * NT];

// Tag layout flag (harness may store int64 or int32; JAX demotes int64->int32).
__device__ int g_tag_shift;   // 0: tags int32; 1: tags int64 (read low word)

// Per-batch mask bitmask: bit (t&31) of g_mbits[b][t>>5] = mask[b][t] != 0.
__device__ unsigned int g_mbits[NB][SEQ / 32];

// Warp max of a POSITIVE float via integer redux (bit pattern monotone for x>0).
// (redux.sync.*.u32 is sm_80+; the .f32 variant is NOT supported on sm_103.)
__device__ __forceinline__ float redux_max_pos(float v) {
    unsigned int r;
    asm volatile("redux.sync.max.u32 %0, %1, 0xffffffff;"
                 : "=r"(r) : "r"(__float_as_uint(v)));
    return __uint_as_float(r);
}

// Warp max of an arbitrary float: monotone map to u32, redux, map back.
__device__ __forceinline__ float redux_max_any(float v) {
    unsigned int b = __float_as_uint(v);
    unsigned int k = ((int)b < 0) ? ~b : (b | 0x80000000u);
    unsigned int r;
    asm volatile("redux.sync.max.u32 %0, %1, 0xffffffff;" : "=r"(r) : "r"(k));
    return __uint_as_float(((int)r < 0) ? (r & 0x7FFFFFFFu) : ~r);
}

// One setup kernel, 3 roles by blockIdx:
//  blocks [0,128)   : pack exp(transitions) into g_Epack (bf16)
//  block  128       : detect tag storage layout -> g_tag_shift
//  blocks [129,193) : detect mask layout locally + pack mask bits for batch b
__global__ void crf_setup_kernel(const float* __restrict__ trans,
                                 const int* __restrict__ tags_raw,
                                 const unsigned int* __restrict__ mask_raw) {
    const int blk = blockIdx.x;
    const int tid = threadIdx.x;

    if (blk < 128) {
        int idx = blk * 256 + tid;              // 0 .. 32767
        int k = idx >> 8;
        int j = idx & (NT - 1);
        float e0 = __expf(trans[(2 * k) * NT + j]);
        float e1 = __expf(trans[(2 * k + 1) * NT + j]);
        g_Epack[idx] = __floats2bfloat162_rn(e0, e1);
        return;
    }

    if (blk == 128) {
        // tags: int64 layout => every odd 32-bit word is the (zero) high half.
        __shared__ int s_odd;
        if (tid == 0) s_odd = 0;
        __syncthreads();
        int any_odd = 0;
        for (int i = tid; i < 512; i += 256) any_odd |= tags_raw[2 * i + 1];
#pragma unroll
        for (int off = 16; off > 0; off >>= 1)
            any_odd |= __shfl_xor_sync(0xffffffffu, any_odd, off);
        if ((tid & 31) == 0) atomicOr(&s_odd, any_odd);
        __syncthreads();
        if (tid == 0) g_tag_shift = (s_odd == 0) ? 1 : 0;
        return;
    }

    // ---- mask pack for batch b ----
    const int b = blk - 129;
    __shared__ int s_up;
    if (tid == 0) s_up = 0;
    __syncthreads();
    // layout detect (global property; sample the first 1024 words)
    int upper = 0;
    for (int i = tid; i < 1024; i += 256) upper |= (int)(mask_raw[i] & 0xFFFFFF00u);
#pragma unroll
    for (int off = 16; off > 0; off >>= 1)
        upper |= __shfl_xor_sync(0xffffffffu, upper, off);
    if ((tid & 31) == 0) atomicOr(&s_up, upper);
    __syncthreads();
    const int msh = (s_up == 0) ? 2 : 0;   // 0: uint8 layout, 2: int32 layout
    const unsigned char* mk8 = (const unsigned char*)mask_raw;
    const size_t base = (size_t)b * SEQ;
    const int wid = tid >> 5;
#pragma unroll
    for (int r = 0; r < 4; ++r) {
        int idx = r * 256 + tid;               // t within the sequence
        unsigned int byte = mk8[(base + idx) << msh];
        unsigned int word = __ballot_sync(0xffffffffu, byte != 0);
        if ((tid & 31) == 0) g_mbits[b][r * 8 + wid] = word;
    }
}

__global__ __launch_bounds__(256, 1)
void crf_fwd_kernel(const float* __restrict__ inputs,
                    const void* __restrict__ tags_v,
                    const float* __restrict__ trans,
                    const float* __restrict__ start_t,
                    const float* __restrict__ stop_t,
                    float* __restrict__ out) {
    // Double-buffered normalized alpha (bf16) and per-warp max scratch:
    // one __syncthreads per step (write buf[t&1] -> read next step), no WAR barrier.
    __shared__ __align__(16) __nv_bfloat16 abuf[2][NT];
    __shared__ __align__(16) float wred[2][8];

    const int j    = threadIdx.x;
    const int b    = blockIdx.x;
    const int lane = j & 31;
    const int wid  = j >> 5;

    const int tsh = g_tag_shift;
    const int* tg32 = (const int*)tags_v;
    const unsigned int* mrow = g_mbits[b];

    // This thread's column of E in registers: 128 bf162 = rows (2k,2k+1), col j.
    __nv_bfloat162 Ereg[128];
#pragma unroll
    for (int k = 0; k < 128; ++k) Ereg[k] = g_Epack[k * NT + j];

    const float* x = inputs + (size_t)b * SEQ * NT;
    const size_t rowbase = (size_t)b * SEQ;

    // ---- init: alpha0 = start + x0; a = exp(alpha0 - M0); Csum = M0 ----
    float alpha0 = start_t[j] + x[j];
    {
        float m = redux_max_any(alpha0);
        if (lane == 0) wred[1][wid] = m;
    }
    __syncthreads();
    float M0;
    {
        float4 w0 = *reinterpret_cast<const float4*>(wred[1]);
        float4 w1 = *reinterpret_cast<const float4*>(wred[1] + 4);
        M0 = fmaxf(fmaxf(fmaxf(w0.x, w0.y), fmaxf(w0.z, w0.w)),
                   fmaxf(fmaxf(w1.x, w1.y), fmaxf(w1.z, w1.w)));
    }
    __nv_bfloat16 a_self = __float2bfloat16(__expf(alpha0 - M0));
    abuf[0][j] = a_self;
    if (j < 8) wred[0][j] = 1.0f;   // seed: divisor for step 1 = 32*sqrt(1) = 32
    float Csum = M0;
    __syncthreads();

    float emit = x[NT + j];           // prefetch t = 1
    unsigned int mw = mrow[0];        // mask bits for t in [0,32)

#pragma unroll 4
    for (int t = 1; t < SEQ - 1; ++t) {
        const int rb = (t + 1) & 1;   // holds a (and warp maxima) from step t-1
        const int wb = t & 1;

        if ((t & 31) == 0) mw = mrow[t >> 5];
        const unsigned int bit = (mw >> (t & 31)) & 1u;

        // ---- off-chain: DAMPED stale divisor V = 32 * sqrt(U_{t-1}) ----
        // Full stale correction has poles on the unit circle (resonant ->
        // NaN, R9/R11). The sqrt gain-1/2 damps to |z|=0.707; bf16 range
        // absorbs residual excursions.
        float4 w0 = *reinterpret_cast<const float4*>(wred[rb]);
        float4 w1 = *reinterpret_cast<const float4*>(wred[rb] + 4);
        float U = fmaxf(fmaxf(fmaxf(w0.x, w0.y), fmaxf(w0.z, w0.w)),
                        fmaxf(fmaxf(w1.x, w1.y), fmaxf(w1.z, w1.w)));
        float rcpV = rsqrtf(U) * 0.03125f;             // 1/(32*sqrt(U))
        float logV = 3.4657359028f + 0.5f * __logf(U); // log32 + log(U)/2

        float eemit = __expf(emit);
        float emit_nx = x[(size_t)(t + 1) * NT + j];   // prefetch next step

        // ---- s_j = sum_i a_i * E[i][j] : bf16 HFMA2, 4 accumulators ----
        __nv_bfloat162 acc0 = __floats2bfloat162_rn(0.f, 0.f);
        __nv_bfloat162 acc1 = acc0, acc2 = acc0, acc3 = acc0;
        const uint4* A4 = reinterpret_cast<const uint4*>(abuf[rb]);
#pragma unroll
        for (int c = 0; c < 32; ++c) {
            uint4 av = A4[c];
            acc0 = __hfma2(*reinterpret_cast<__nv_bfloat162*>(&av.x), Ereg[4 * c + 0], acc0);
            acc1 = __hfma2(*reinterpret_cast<__nv_bfloat162*>(&av.y), Ereg[4 * c + 1], acc1);
            acc2 = __hfma2(*reinterpret_cast<__nv_bfloat162*>(&av.z), Ereg[4 * c + 2], acc2);
            acc3 = __hfma2(*reinterpret_cast<__nv_bfloat162*>(&av.w), Ereg[4 * c + 3], acc3);
        }
        __nv_bfloat162 accA = __hadd2(__hadd2(acc0, acc1), __hadd2(acc2, acc3));
        float2 fA = __bfloat1622float2(accA);
        float s = fA.x + fA.y;

        // u_j = s_j * exp(emit_j)  (strictly positive)
        float u = s * eemit;

        // tail (parallel paths): warp max for NEXT step's divisor | a = u/V
        float um = redux_max_pos(u);
        if (lane == 0) wred[wb][wid] = um;

        __nv_bfloat16 anew = __float2bfloat16(u * rcpV);
        a_self = bit ? anew : a_self;       // mask==0: freeze (alpha = Csum + log a)
        abuf[wb][j] = a_self;
        Csum += bit ? logV : 0.f;           // same divisor -> invariant exact

        __syncthreads();
        emit = emit_nx;
    }

    // ---- peeled final step t = SEQ-1 (no prefetch, no clamp) ----
    {
        const int t = SEQ - 1;
        const int rb = (t + 1) & 1;
        const unsigned int bit = (mw >> (t & 31)) & 1u;

        float4 w0 = *reinterpret_cast<const float4*>(wred[rb]);
        float4 w1 = *reinterpret_cast<const float4*>(wred[rb] + 4);
        float U = fmaxf(fmaxf(fmaxf(w0.x, w0.y), fmaxf(w0.z, w0.w)),
                        fmaxf(fmaxf(w1.x, w1.y), fmaxf(w1.z, w1.w)));
        float rcpV = rsqrtf(U) * 0.03125f;
        float logV = 3.4657359028f + 0.5f * __logf(U);
        float eemit = __expf(emit);

        __nv_bfloat162 acc0 = __floats2bfloat162_rn(0.f, 0.f);
        __nv_bfloat162 acc1 = acc0, acc2 = acc0, acc3 = acc0;
        const uint4* A4 = reinterpret_cast<const uint4*>(abuf[rb]);
#pragma unroll
        for (int c = 0; c < 32; ++c) {
            uint4 av = A4[c];
            acc0 = __hfma2(*reinterpret_cast<__nv_bfloat162*>(&av.x), Ereg[4 * c + 0], acc0);
            acc1 = __hfma2(*reinterpret_cast<__nv_bfloat162*>(&av.y), Ereg[4 * c + 1], acc1);
            acc2 = __hfma2(*reinterpret_cast<__nv_bfloat162*>(&av.z), Ereg[4 * c + 2], acc2);
            acc3 = __hfma2(*reinterpret_cast<__nv_bfloat162*>(&av.w), Ereg[4 * c + 3], acc3);
        }
        __nv_bfloat162 accA = __hadd2(__hadd2(acc0, acc1), __hadd2(acc2, acc3));
        float2 fA = __bfloat1622float2(accA);
        float u = (fA.x + fA.y) * eemit;

        __nv_bfloat16 anew = __float2bfloat16(u * rcpV);
        a_self = bit ? anew : a_self;
        Csum += bit ? logV : 0.f;
    }

    float alpha = Csum + __logf(__bfloat162float(a_self));

    // ---- denominator: logsumexp_j(alpha_j + stop_j) ----
    float v = alpha + stop_t[j];
    {
        float m = redux_max_any(v);
        if (lane == 0) wred[0][wid] = m;
    }
    __syncthreads();
    float Md;
    {
        float4 w0 = *reinterpret_cast<const float4*>(wred[0]);
        float4 w1 = *reinterpret_cast<const float4*>(wred[0] + 4);
        Md = fmaxf(fmaxf(fmaxf(w0.x, w0.y), fmaxf(w0.z, w0.w)),
                   fmaxf(fmaxf(w1.x, w1.y), fmaxf(w1.z, w1.w)));
    }
    __syncthreads();
    float e = __expf(v - Md);
#pragma unroll
    for (int off = 16; off > 0; off >>= 1)
        e += __shfl_xor_sync(0xffffffffu, e, off);
    if (lane == 0) wred[0][wid] = e;
    __syncthreads();
    float tot = 0.f;
#pragma unroll
    for (int w = 0; w < 8; ++w) tot += wred[0][w];
    float denom = Md + __logf(tot);

    // ---- numerator (gather score) ----
    float part = 0.f;
    for (int t = j; t < SEQ; t += 256) {
        int   tag = tg32[(rowbase + t) << tsh];
        float mf  = (float)((mrow[t >> 5] >> (t & 31)) & 1u);
        if (t == 0) part += start_t[tag];
        else {
            int ptag = tg32[(rowbase + t - 1) << tsh];
            part += trans[ptag * NT + tag] * mf;
        }
        float em = x[(size_t)t * NT + tag];
        if (t < SEQ - 1) part += em * mf;
        else             part += (stop_t[tag] + em) * mf;
    }
#pragma unroll
    for (int off = 16; off > 0; off >>= 1)
        part += __shfl_xor_sync(0xffffffffu, part, off);
    __syncthreads();
    if (lane == 0) wred[0][wid] = part;
    __syncthreads();
    if (j == 0) {
        float num = 0.f;
#pragma unroll
        for (int w = 0; w < 8; ++w) num += wred[0][w];
        out[b] = num - denom;
    }
}

extern "C" void kernel_launch(void* const* d_in, const int* in_sizes, int n_in,
                              void* d_out, int out_size) {
    const float* inputs  = (const float*)d_in[0];
    const void*  tags    = d_in[1];
    const void*  mask    = d_in[2];
    const float* trans   = (const float*)d_in[3];
    const float* start_t = (const float*)d_in[4];
    const float* stop_t  = (const float*)d_in[5];
    float*       out     = (float*)d_out;

    crf_setup_kernel<<<193, 256>>>(trans, (const int*)tags, (const unsigned int*)mask);
    crf_fwd_kernel<<<NB, 256>>>(inputs, tags, trans, start_t, stop_t, out);
}